// round 5
// baseline (speedup 1.0000x reference)
#include <cuda_runtime.h>
#include <math.h>

#define T_VOCAB 50265
#define CTX     384
#define BS      4
#define NDS     2048
#define NQ      4                  // vocab quarters (CTAs per position)

// scratch (allocation-free rule: __device__ globals)
__device__ int      g_mc[BS * NDS];
__device__ float    g_w [BS * NDS];
__device__ int      g_dt[CTX * NDS];      // transposed dataset: g_dt[s*NDS + n]
__device__ unsigned g_st[CTX * NDS];      // per-s sorted keys: (token<<11) | n

// ---------------------------------------------------------------------------
// Kernel T: tiled transpose dataset (n,s) -> g_dt (s,n) for coalesced columns.
// ---------------------------------------------------------------------------
__global__ void transpose_kernel(const int* __restrict__ dataset) {
    __shared__ int tile[32][33];
    const int n0 = blockIdx.x * 32;
    const int s0 = blockIdx.y * 32;
    const int tx = threadIdx.x, ty = threadIdx.y;  // 32 x 8
    #pragma unroll
    for (int i = 0; i < 32; i += 8)
        tile[ty + i][tx] = dataset[(n0 + ty + i) * CTX + s0 + tx];
    __syncthreads();
    #pragma unroll
    for (int i = 0; i < 32; i += 8)
        g_dt[(s0 + ty + i) * NDS + n0 + tx] = tile[tx][ty + i];
}

// ---------------------------------------------------------------------------
// Kernel A: match counts. One warp per dataset row n; vectorized int4 loads.
// ---------------------------------------------------------------------------
__global__ void mc_kernel(const int* __restrict__ input,
                          const int* __restrict__ dataset) {
    __shared__ int4 s_in[BS][CTX / 4];
    const int tid = threadIdx.x;
    for (int i = tid; i < BS * CTX / 4; i += blockDim.x)
        (&s_in[0][0])[i] = ((const int4*)input)[i];
    __syncthreads();

    const int warp = tid >> 5, lane = tid & 31;
    const int n = blockIdx.x * (blockDim.x >> 5) + warp;
    const int4* row = (const int4*)(dataset + n * CTX);

    int c0 = 0, c1 = 0, c2 = 0, c3 = 0;
    #pragma unroll
    for (int i = 0; i < 3; i++) {
        const int idx = lane + 32 * i;
        const int4 dv = row[idx];
        int4 a;
        a = s_in[0][idx];
        c0 += (dv.x == a.x) + (dv.y == a.y) + (dv.z == a.z) + (dv.w == a.w);
        a = s_in[1][idx];
        c1 += (dv.x == a.x) + (dv.y == a.y) + (dv.z == a.z) + (dv.w == a.w);
        a = s_in[2][idx];
        c2 += (dv.x == a.x) + (dv.y == a.y) + (dv.z == a.z) + (dv.w == a.w);
        a = s_in[3][idx];
        c3 += (dv.x == a.x) + (dv.y == a.y) + (dv.z == a.z) + (dv.w == a.w);
    }
    #pragma unroll
    for (int off = 16; off > 0; off >>= 1) {
        c0 += __shfl_down_sync(0xffffffffu, c0, off);
        c1 += __shfl_down_sync(0xffffffffu, c1, off);
        c2 += __shfl_down_sync(0xffffffffu, c2, off);
        c3 += __shfl_down_sync(0xffffffffu, c3, off);
    }
    if (lane == 0) {
        g_mc[0 * NDS + n] = c0;
        g_mc[1 * NDS + n] = c1;
        g_mc[2 * NDS + n] = c2;
        g_mc[3 * NDS + n] = c3;
    }
}

// ---------------------------------------------------------------------------
// Kernel B: softmax over dataset axis per batch; depends only on mc * d.
// ---------------------------------------------------------------------------
__global__ void softmax_kernel(const float* __restrict__ t) {
    const int b   = blockIdx.x;
    const int tid = threadIdx.x;
    const float tb = t[b];
    const float d = logf(1.0f + tb * (float)T_VOCAB / (1.0f - tb));

    __shared__ int   s_max[256];
    __shared__ float s_sum[256];

    int mymax = -1;
    for (int n = tid; n < NDS; n += 256) mymax = max(mymax, g_mc[b * NDS + n]);
    s_max[tid] = mymax;
    __syncthreads();
    for (int off = 128; off > 0; off >>= 1) {
        if (tid < off) s_max[tid] = max(s_max[tid], s_max[tid + off]);
        __syncthreads();
    }
    const int mcmax = s_max[0];

    float mysum = 0.0f;
    for (int n = tid; n < NDS; n += 256) {
        float e = expf((float)(g_mc[b * NDS + n] - mcmax) * d);
        g_w[b * NDS + n] = e;
        mysum += e;
    }
    s_sum[tid] = mysum;
    __syncthreads();
    for (int off = 128; off > 0; off >>= 1) {
        if (tid < off) s_sum[tid] += s_sum[tid + off];
        __syncthreads();
    }
    const float inv = 1.0f / s_sum[0];
    __syncthreads();
    for (int n = tid; n < NDS; n += 256) g_w[b * NDS + n] *= inv;
}

// ---------------------------------------------------------------------------
// Kernel S: per-position bitonic sort of packed keys (token<<11 | n).
// ---------------------------------------------------------------------------
__global__ __launch_bounds__(512)
void sort_kernel() {
    __shared__ unsigned key[NDS];
    const int s = blockIdx.x, tid = threadIdx.x;

    for (int i = tid; i < NDS; i += 512)
        key[i] = ((unsigned)g_dt[s * NDS + i] << 11) | (unsigned)i;
    __syncthreads();

    for (int k = 2; k <= NDS; k <<= 1) {
        for (int j = k >> 1; j > 0; j >>= 1) {
            #pragma unroll 1
            for (int m = tid; m < NDS / 2; m += 512) {
                const int i   = ((m & ~(j - 1)) << 1) | (m & (j - 1));
                const int ixj = i | j;
                const unsigned a = key[i], b = key[ixj];
                const bool up = ((i & k) == 0);
                if ((a > b) == up) { key[i] = b; key[ixj] = a; }
            }
            __syncthreads();
        }
    }
    for (int i = tid; i < NDS; i += 512)
        g_st[s * NDS + i] = key[i];
}

// ---------------------------------------------------------------------------
// Kernel C: merge-streaming scatter. One CTA per (s, vocab-quarter), covering
// all 4 batches. Each warp owns a contiguous vocab range: binary search once,
// then stream 128-entry windows (1 float4/lane), accumulating in-range sorted
// tokens into registers and emitting 4 coalesced STG.128 per window. No
// atomics, no zero-fill pass, no smem slab: exactly one L1/DRAM pass per
// output byte.
// ---------------------------------------------------------------------------
__global__ __launch_bounds__(512, 2)
void scatter_kernel(float* __restrict__ out) {
    __shared__ unsigned st[NDS];      // sorted keys for this s
    __shared__ float4   wr4[NDS];     // weights for all 4 batches, indexed by n

    const int s    = blockIdx.x;
    const int q    = blockIdx.y;
    const int tid  = threadIdx.x;
    const int lane = tid & 31;
    const int warp = tid >> 5;

    for (int i = tid; i < NDS; i += 512) st[i] = g_st[s * NDS + i];
    for (int i = tid; i < NDS; i += 512)
        wr4[i] = make_float4(g_w[i], g_w[NDS + i], g_w[2 * NDS + i], g_w[3 * NDS + i]);
    __syncthreads();

    // row geometry: base mod 4 == s mod 4 for every b (384 % 4 == 0)
    const int head = (4 - (s & 3)) & 3;            // scalar entries at row start
    const int K    = (T_VOCAB - head) >> 2;        // aligned float4 chunks
    const int R    = (T_VOCAB - head) & 3;         // scalar entries at row end
    const int Kq   = (K + NQ - 1) / NQ;            // chunks per quarter
    const int Wq   = (Kq + 15) >> 4;               // chunks per warp

    const size_t b0 = ((size_t)(0 * CTX + s)) * T_VOCAB;
    const size_t b1 = ((size_t)(1 * CTX + s)) * T_VOCAB;
    const size_t b2 = ((size_t)(2 * CTX + s)) * T_VOCAB;
    const size_t b3 = ((size_t)(3 * CTX + s)) * T_VOCAB;

    const int lim    = min((q + 1) * Kq, K);
    const int cstart = q * Kq + warp * Wq;
    const int cend   = min(cstart + Wq, lim);

    if (cstart < cend) {
        // lower_bound for first token >= this warp's range start
        const unsigned target = (unsigned)(head + 4 * cstart) << 11;
        int lo = 0, hi = NDS;
        while (lo < hi) {
            const int mid = (lo + hi) >> 1;
            if (st[mid] < target) lo = mid + 1; else hi = mid;
        }
        int p = lo;

        for (int c = cstart; c < cend; c += 32) {
            const int wlen  = min(32, cend - c);
            const int vbase = head + 4 * c;
            const int vend  = vbase + 4 * wlen;

            float4 a0 = make_float4(0.f, 0.f, 0.f, 0.f);
            float4 a1 = a0, a2 = a0, a3 = a0;

            while (p < NDS) {
                const unsigned key = st[p];           // LDS broadcast
                const int tok = (int)(key >> 11);
                if (tok >= vend) break;
                const float4 wv = wr4[key & (NDS - 1)];
                const int rel = tok - vbase;
                const int li  = rel >> 2;
                const int ci  = rel & 3;              // warp-uniform
                if (lane == li) {
                    if (ci == 0)      { a0.x += wv.x; a1.x += wv.y; a2.x += wv.z; a3.x += wv.w; }
                    else if (ci == 1) { a0.y += wv.x; a1.y += wv.y; a2.y += wv.z; a3.y += wv.w; }
                    else if (ci == 2) { a0.z += wv.x; a1.z += wv.y; a2.z += wv.z; a3.z += wv.w; }
                    else              { a0.w += wv.x; a1.w += wv.y; a2.w += wv.z; a3.w += wv.w; }
                }
                p++;
            }

            if (lane < wlen) {
                const int off = vbase + 4 * lane;     // 16B aligned (head fix)
                *reinterpret_cast<float4*>(out + b0 + off) = a0;
                *reinterpret_cast<float4*>(out + b1 + off) = a1;
                *reinterpret_cast<float4*>(out + b2 + off) = a2;
                *reinterpret_cast<float4*>(out + b3 + off) = a3;
            }
        }
    }

    // head entries: vocab ids [0, head) — handled by quarter 0
    if (q == 0 && tid < head) {
        const int v = tid;
        float acc0 = 0.f, acc1 = 0.f, acc2 = 0.f, acc3 = 0.f;
        for (int p2 = 0; p2 < NDS; p2++) {
            const unsigned key = st[p2];
            const int tok = (int)(key >> 11);
            if (tok > v) break;
            if (tok == v) {
                const float4 wv = wr4[key & (NDS - 1)];
                acc0 += wv.x; acc1 += wv.y; acc2 += wv.z; acc3 += wv.w;
            }
        }
        out[b0 + v] = acc0; out[b1 + v] = acc1;
        out[b2 + v] = acc2; out[b3 + v] = acc3;
    }

    // tail entries: vocab ids [T_VOCAB - R, T_VOCAB) — handled by quarter 3
    if (q == NQ - 1 && tid < R) {
        const int v = T_VOCAB - R + tid;
        const unsigned target = (unsigned)v << 11;
        int lo = 0, hi = NDS;
        while (lo < hi) {
            const int mid = (lo + hi) >> 1;
            if (st[mid] < target) lo = mid + 1; else hi = mid;
        }
        float acc0 = 0.f, acc1 = 0.f, acc2 = 0.f, acc3 = 0.f;
        for (int p2 = lo; p2 < NDS; p2++) {
            const unsigned key = st[p2];
            if ((int)(key >> 11) != v) break;
            const float4 wv = wr4[key & (NDS - 1)];
            acc0 += wv.x; acc1 += wv.y; acc2 += wv.z; acc3 += wv.w;
        }
        out[b0 + v] = acc0; out[b1 + v] = acc1;
        out[b2 + v] = acc2; out[b3 + v] = acc3;
    }
}

// ---------------------------------------------------------------------------
extern "C" void kernel_launch(void* const* d_in, const int* in_sizes, int n_in,
                              void* d_out, int out_size) {
    const int*   input   = (const int*)d_in[0];    // (4, 384)
    const int*   dataset = (const int*)d_in[1];    // (2048, 384)
    const float* t       = (const float*)d_in[2];  // (4,)
    float* out = (float*)d_out;                    // (4, 384, 50265) f32

    // T: transpose dataset for coalesced column reads
    dim3 tgrid(NDS / 32, CTX / 32);
    transpose_kernel<<<tgrid, dim3(32, 8)>>>(dataset);

    // A: match counts
    mc_kernel<<<NDS / 8, 256>>>(input, dataset);

    // B: softmax weights
    softmax_kernel<<<BS, 256>>>(t);

    // S: per-position sorted token keys
    sort_kernel<<<CTX, 512>>>();

    // C: merge-streaming scatter, one CTA per (position, vocab-quarter)
    dim3 grid(CTX, NQ);
    scatter_kernel<<<grid, 512>>>(out);
}

// round 6
// speedup vs baseline: 1.2203x; 1.2203x over previous
#include <cuda_runtime.h>
#include <math.h>

#define T_VOCAB 50265
#define CTX     384
#define BS      4
#define NDS     2048
#define NQ      4                  // vocab quarters (CTAs per position)
#define NBINS   394                // bin 0 = head tokens, bins 1..393 = windows
#define BSLEN   (NBINS + 1)

// scratch (allocation-free rule: __device__ globals)
__device__ int      g_mc[BS * NDS];
__device__ float    g_w [BS * NDS];
__device__ int      g_dt[CTX * NDS];        // transposed dataset: g_dt[s*NDS+n]
__device__ unsigned g_sk[CTX * NDS];        // per-s bin-grouped keys (tok<<11|n)
__device__ int      g_bs[CTX * BSLEN];      // per-s bin start offsets

// ---------------------------------------------------------------------------
// Kernel T: tiled transpose dataset (n,s) -> g_dt (s,n) for coalesced columns.
// ---------------------------------------------------------------------------
__global__ void transpose_kernel(const int* __restrict__ dataset) {
    __shared__ int tile[32][33];
    const int n0 = blockIdx.x * 32;
    const int s0 = blockIdx.y * 32;
    const int tx = threadIdx.x, ty = threadIdx.y;  // 32 x 8
    #pragma unroll
    for (int i = 0; i < 32; i += 8)
        tile[ty + i][tx] = dataset[(n0 + ty + i) * CTX + s0 + tx];
    __syncthreads();
    #pragma unroll
    for (int i = 0; i < 32; i += 8)
        g_dt[(s0 + ty + i) * NDS + n0 + tx] = tile[tx][ty + i];
}

// ---------------------------------------------------------------------------
// Kernel A: match counts. One warp per dataset row n; vectorized int4 loads.
// ---------------------------------------------------------------------------
__global__ void mc_kernel(const int* __restrict__ input,
                          const int* __restrict__ dataset) {
    __shared__ int4 s_in[BS][CTX / 4];
    const int tid = threadIdx.x;
    for (int i = tid; i < BS * CTX / 4; i += blockDim.x)
        (&s_in[0][0])[i] = ((const int4*)input)[i];
    __syncthreads();

    const int warp = tid >> 5, lane = tid & 31;
    const int n = blockIdx.x * (blockDim.x >> 5) + warp;
    const int4* row = (const int4*)(dataset + n * CTX);

    int c0 = 0, c1 = 0, c2 = 0, c3 = 0;
    #pragma unroll
    for (int i = 0; i < 3; i++) {
        const int idx = lane + 32 * i;
        const int4 dv = row[idx];
        int4 a;
        a = s_in[0][idx];
        c0 += (dv.x == a.x) + (dv.y == a.y) + (dv.z == a.z) + (dv.w == a.w);
        a = s_in[1][idx];
        c1 += (dv.x == a.x) + (dv.y == a.y) + (dv.z == a.z) + (dv.w == a.w);
        a = s_in[2][idx];
        c2 += (dv.x == a.x) + (dv.y == a.y) + (dv.z == a.z) + (dv.w == a.w);
        a = s_in[3][idx];
        c3 += (dv.x == a.x) + (dv.y == a.y) + (dv.z == a.z) + (dv.w == a.w);
    }
    #pragma unroll
    for (int off = 16; off > 0; off >>= 1) {
        c0 += __shfl_down_sync(0xffffffffu, c0, off);
        c1 += __shfl_down_sync(0xffffffffu, c1, off);
        c2 += __shfl_down_sync(0xffffffffu, c2, off);
        c3 += __shfl_down_sync(0xffffffffu, c3, off);
    }
    if (lane == 0) {
        g_mc[0 * NDS + n] = c0;
        g_mc[1 * NDS + n] = c1;
        g_mc[2 * NDS + n] = c2;
        g_mc[3 * NDS + n] = c3;
    }
}

// ---------------------------------------------------------------------------
// Kernel B: softmax over dataset axis per batch; depends only on mc * d.
// ---------------------------------------------------------------------------
__global__ void softmax_kernel(const float* __restrict__ t) {
    const int b   = blockIdx.x;
    const int tid = threadIdx.x;
    const float tb = t[b];
    const float d = logf(1.0f + tb * (float)T_VOCAB / (1.0f - tb));

    __shared__ int   s_max[256];
    __shared__ float s_sum[256];

    int mymax = -1;
    for (int n = tid; n < NDS; n += 256) mymax = max(mymax, g_mc[b * NDS + n]);
    s_max[tid] = mymax;
    __syncthreads();
    for (int off = 128; off > 0; off >>= 1) {
        if (tid < off) s_max[tid] = max(s_max[tid], s_max[tid + off]);
        __syncthreads();
    }
    const int mcmax = s_max[0];

    float mysum = 0.0f;
    for (int n = tid; n < NDS; n += 256) {
        float e = expf((float)(g_mc[b * NDS + n] - mcmax) * d);
        g_w[b * NDS + n] = e;
        mysum += e;
    }
    s_sum[tid] = mysum;
    __syncthreads();
    for (int off = 128; off > 0; off >>= 1) {
        if (tid < off) s_sum[tid] += s_sum[tid + off];
        __syncthreads();
    }
    const float inv = 1.0f / s_sum[0];
    __syncthreads();
    for (int n = tid; n < NDS; n += 256) g_w[b * NDS + n] *= inv;
}

// ---------------------------------------------------------------------------
// Kernel H: per-position bucketing (replaces bitonic sort). Histogram the
// 2048 tokens into 394 bins of 128 vocab ids (relative to the row's float4
// alignment head), warp-scan the bin counts, then scatter packed keys into
// bin-grouped order. Order within a bin is irrelevant downstream.
// ---------------------------------------------------------------------------
__global__ __launch_bounds__(512)
void bucket_kernel() {
    __shared__ int hist[NBINS];
    __shared__ int bs[BSLEN];
    __shared__ int cur[NBINS];

    const int s    = blockIdx.x;
    const int tid  = threadIdx.x;
    const int lane = tid & 31;
    const int warp = tid >> 5;
    const int head = (4 - (s & 3)) & 3;

    for (int i = tid; i < NBINS; i += 512) hist[i] = 0;
    __syncthreads();

    int  my_tok[4];
    int  my_bin[4];
    #pragma unroll
    for (int k = 0; k < 4; k++) {
        const int n = tid + 512 * k;
        const int tok = g_dt[s * NDS + n];
        my_tok[k] = tok;
        my_bin[k] = (tok - head + 128) >> 7;   // head tokens -> bin 0
        atomicAdd(&hist[my_bin[k]], 1);
    }
    __syncthreads();

    // exclusive prefix over NBINS bins: warp 0 only, 13 bins per lane
    if (warp == 0) {
        const int base = lane * 13;            // 32*13 = 416 >= 394
        int local[13];
        int sum = 0;
        #pragma unroll
        for (int k = 0; k < 13; k++) {
            const int idx = base + k;
            const int v = (idx < NBINS) ? hist[idx] : 0;
            local[k] = sum;
            sum += v;
        }
        // exclusive scan of per-lane sums
        int incl = sum;
        #pragma unroll
        for (int off = 1; off < 32; off <<= 1) {
            const int y = __shfl_up_sync(0xffffffffu, incl, off);
            if (lane >= off) incl += y;
        }
        const int excl = incl - sum;
        #pragma unroll
        for (int k = 0; k < 13; k++) {
            const int idx = base + k;
            if (idx < NBINS) { bs[idx] = excl + local[k]; cur[idx] = excl + local[k]; }
        }
        if (lane == 0) bs[NBINS] = NDS;
    }
    __syncthreads();

    #pragma unroll
    for (int k = 0; k < 4; k++) {
        const int n   = tid + 512 * k;
        const int pos = atomicAdd(&cur[my_bin[k]], 1);
        g_sk[s * NDS + pos] = ((unsigned)my_tok[k] << 11) | (unsigned)n;
    }
    __syncthreads();

    for (int i = tid; i < BSLEN; i += 512)
        g_bs[s * BSLEN + i] = bs[i];
}

// ---------------------------------------------------------------------------
// Kernel C: merge-streaming scatter. One CTA per (s, vocab-quarter), all 4
// batches together. Each warp owns ~7 global 128-float windows; per window it
// reads that bin's keys straight from global (L1/L2-resident), accumulates
// into registers, and emits 4 coalesced STG.128. No smem, no sync, no
// atomics, no zero pass: exactly one DRAM pass per output byte.
// ---------------------------------------------------------------------------
__global__ __launch_bounds__(512)
void scatter_kernel(float* __restrict__ out) {
    const int s    = blockIdx.x;
    const int q    = blockIdx.y;
    const int tid  = threadIdx.x;
    const int lane = tid & 31;
    const int warp = tid >> 5;

    const int head = (4 - (s & 3)) & 3;
    const int K    = (T_VOCAB - head) >> 2;        // aligned float4 chunks
    const int R    = (T_VOCAB - head) & 3;         // trailing scalars
    const int NW   = (K + 31) >> 5;                // 128-float windows (=393)
    const int NWq  = (NW + NQ - 1) / NQ;           // windows per quarter
    const int Ww   = (NWq + 15) >> 4;              // windows per warp

    const size_t b0 = ((size_t)(0 * CTX + s)) * T_VOCAB;
    const size_t b1 = ((size_t)(1 * CTX + s)) * T_VOCAB;
    const size_t b2 = ((size_t)(2 * CTX + s)) * T_VOCAB;
    const size_t b3 = ((size_t)(3 * CTX + s)) * T_VOCAB;

    const int lim = min((q + 1) * NWq, NW);
    const int w0  = q * NWq + warp * Ww;
    const int w1  = min(w0 + Ww, lim);

    const unsigned* sk = g_sk + s * NDS;
    const int*      bsp = g_bs + s * BSLEN;

    for (int w = w0; w < w1; w++) {
        const int vbase = head + 128 * w;
        const int wlen  = min(32, K - 32 * w);
        const int pst   = __ldg(bsp + w + 1);      // bin w+1 = window w
        const int pen   = __ldg(bsp + w + 2);

        float4 a0 = make_float4(0.f, 0.f, 0.f, 0.f);
        float4 a1 = a0, a2 = a0, a3 = a0;

        for (int p = pst; p < pen; p++) {
            const unsigned key = __ldg(sk + p);    // warp-broadcast
            const int tok = (int)(key >> 11);
            const int rel = tok - vbase;           // in [0,128) by bucketing
            const int li  = rel >> 2;
            const int ci  = rel & 3;
            if (lane == li) {
                const int n = (int)(key & (NDS - 1));
                const float w0v = __ldg(g_w + n);
                const float w1v = __ldg(g_w + NDS + n);
                const float w2v = __ldg(g_w + 2 * NDS + n);
                const float w3v = __ldg(g_w + 3 * NDS + n);
                if (ci == 0)      { a0.x += w0v; a1.x += w1v; a2.x += w2v; a3.x += w3v; }
                else if (ci == 1) { a0.y += w0v; a1.y += w1v; a2.y += w2v; a3.y += w3v; }
                else if (ci == 2) { a0.z += w0v; a1.z += w1v; a2.z += w2v; a3.z += w3v; }
                else              { a0.w += w0v; a1.w += w1v; a2.w += w2v; a3.w += w3v; }
            }
        }

        if (lane < wlen) {
            const int off = vbase + 4 * lane;      // 16B aligned
            *reinterpret_cast<float4*>(out + b0 + off) = a0;
            *reinterpret_cast<float4*>(out + b1 + off) = a1;
            *reinterpret_cast<float4*>(out + b2 + off) = a2;
            *reinterpret_cast<float4*>(out + b3 + off) = a3;
        }

        // trailing scalars (vocab ids beyond the last full chunk): lane==wlen
        // accumulated them with li==wlen, ci==0..R-1.
        if (w == NW - 1 && R > 0 && lane == wlen) {
            const size_t o = (size_t)(vbase + 4 * wlen);
            out[b0 + o] = a0.x; out[b1 + o] = a1.x;
            out[b2 + o] = a2.x; out[b3 + o] = a3.x;
            if (R > 1) {
                out[b0 + o + 1] = a0.y; out[b1 + o + 1] = a1.y;
                out[b2 + o + 1] = a2.y; out[b3 + o + 1] = a3.y;
            }
            if (R > 2) {
                out[b0 + o + 2] = a0.z; out[b1 + o + 2] = a1.z;
                out[b2 + o + 2] = a2.z; out[b3 + o + 2] = a3.z;
            }
        }
    }

    // head scalars (vocab ids [0, head)): bin 0, handled by quarter 0 warp 0
    if (q == 0 && warp == 0 && lane < head) {
        const int v   = lane;
        const int pen = __ldg(bsp + 1);
        float acc0 = 0.f, acc1 = 0.f, acc2 = 0.f, acc3 = 0.f;
        for (int p = 0; p < pen; p++) {
            const unsigned key = __ldg(sk + p);
            if ((int)(key >> 11) == v) {
                const int n = (int)(key & (NDS - 1));
                acc0 += __ldg(g_w + n);
                acc1 += __ldg(g_w + NDS + n);
                acc2 += __ldg(g_w + 2 * NDS + n);
                acc3 += __ldg(g_w + 3 * NDS + n);
            }
        }
        out[b0 + v] = acc0; out[b1 + v] = acc1;
        out[b2 + v] = acc2; out[b3 + v] = acc3;
    }
}

// ---------------------------------------------------------------------------
extern "C" void kernel_launch(void* const* d_in, const int* in_sizes, int n_in,
                              void* d_out, int out_size) {
    const int*   input   = (const int*)d_in[0];    // (4, 384)
    const int*   dataset = (const int*)d_in[1];    // (2048, 384)
    const float* t       = (const float*)d_in[2];  // (4,)
    float* out = (float*)d_out;                    // (4, 384, 50265) f32

    // T: transpose dataset for coalesced column reads
    dim3 tgrid(NDS / 32, CTX / 32);
    transpose_kernel<<<tgrid, dim3(32, 8)>>>(dataset);

    // A: match counts
    mc_kernel<<<NDS / 8, 256>>>(input, dataset);

    // B: softmax weights
    softmax_kernel<<<BS, 256>>>(t);

    // H: per-position window bucketing (O(n), replaces bitonic sort)
    bucket_kernel<<<CTX, 512>>>();

    // C: merge-streaming scatter, one CTA per (position, vocab-quarter)
    dim3 grid(CTX, NQ);
    scatter_kernel<<<grid, 512>>>(out);
}

// round 7
// speedup vs baseline: 1.2752x; 1.0450x over previous
#include <cuda_runtime.h>
#include <math.h>

#define T_VOCAB 50265
#define CTX     384
#define BS      4
#define NDS     2048
#define NQ      4                  // vocab quarters (CTAs per position)
#define NBINS   394                // bin 0 = head tokens, bins 1..393 = windows
#define BSLEN   (NBINS + 1)

// scratch (allocation-free rule: __device__ globals)
__device__ int   g_mc[BS * NDS];
__device__ float g_w [BS * NDS];
__device__ int   g_dt[CTX * NDS];        // transposed dataset: g_dt[s*NDS+n]

// ---------------------------------------------------------------------------
// Kernel T: tiled transpose dataset (n,s) -> g_dt (s,n) for coalesced columns.
// ---------------------------------------------------------------------------
__global__ void transpose_kernel(const int* __restrict__ dataset) {
    __shared__ int tile[32][33];
    const int n0 = blockIdx.x * 32;
    const int s0 = blockIdx.y * 32;
    const int tx = threadIdx.x, ty = threadIdx.y;  // 32 x 8
    #pragma unroll
    for (int i = 0; i < 32; i += 8)
        tile[ty + i][tx] = dataset[(n0 + ty + i) * CTX + s0 + tx];
    __syncthreads();
    #pragma unroll
    for (int i = 0; i < 32; i += 8)
        g_dt[(s0 + ty + i) * NDS + n0 + tx] = tile[tx][ty + i];
}

// ---------------------------------------------------------------------------
// Kernel A: match counts. One warp per dataset row n; vectorized int4 loads.
// ---------------------------------------------------------------------------
__global__ void mc_kernel(const int* __restrict__ input,
                          const int* __restrict__ dataset) {
    __shared__ int4 s_in[BS][CTX / 4];
    const int tid = threadIdx.x;
    for (int i = tid; i < BS * CTX / 4; i += blockDim.x)
        (&s_in[0][0])[i] = ((const int4*)input)[i];
    __syncthreads();

    const int warp = tid >> 5, lane = tid & 31;
    const int n = blockIdx.x * (blockDim.x >> 5) + warp;
    const int4* row = (const int4*)(dataset + n * CTX);

    int c0 = 0, c1 = 0, c2 = 0, c3 = 0;
    #pragma unroll
    for (int i = 0; i < 3; i++) {
        const int idx = lane + 32 * i;
        const int4 dv = row[idx];
        int4 a;
        a = s_in[0][idx];
        c0 += (dv.x == a.x) + (dv.y == a.y) + (dv.z == a.z) + (dv.w == a.w);
        a = s_in[1][idx];
        c1 += (dv.x == a.x) + (dv.y == a.y) + (dv.z == a.z) + (dv.w == a.w);
        a = s_in[2][idx];
        c2 += (dv.x == a.x) + (dv.y == a.y) + (dv.z == a.z) + (dv.w == a.w);
        a = s_in[3][idx];
        c3 += (dv.x == a.x) + (dv.y == a.y) + (dv.z == a.z) + (dv.w == a.w);
    }
    #pragma unroll
    for (int off = 16; off > 0; off >>= 1) {
        c0 += __shfl_down_sync(0xffffffffu, c0, off);
        c1 += __shfl_down_sync(0xffffffffu, c1, off);
        c2 += __shfl_down_sync(0xffffffffu, c2, off);
        c3 += __shfl_down_sync(0xffffffffu, c3, off);
    }
    if (lane == 0) {
        g_mc[0 * NDS + n] = c0;
        g_mc[1 * NDS + n] = c1;
        g_mc[2 * NDS + n] = c2;
        g_mc[3 * NDS + n] = c3;
    }
}

// ---------------------------------------------------------------------------
// Kernel B: softmax over dataset axis per batch; depends only on mc * d.
// ---------------------------------------------------------------------------
__global__ void softmax_kernel(const float* __restrict__ t) {
    const int b   = blockIdx.x;
    const int tid = threadIdx.x;
    const float tb = t[b];
    const float d = logf(1.0f + tb * (float)T_VOCAB / (1.0f - tb));

    __shared__ int   s_max[256];
    __shared__ float s_sum[256];

    int mymax = -1;
    for (int n = tid; n < NDS; n += 256) mymax = max(mymax, g_mc[b * NDS + n]);
    s_max[tid] = mymax;
    __syncthreads();
    for (int off = 128; off > 0; off >>= 1) {
        if (tid < off) s_max[tid] = max(s_max[tid], s_max[tid + off]);
        __syncthreads();
    }
    const int mcmax = s_max[0];

    float mysum = 0.0f;
    for (int n = tid; n < NDS; n += 256) {
        float e = expf((float)(g_mc[b * NDS + n] - mcmax) * d);
        g_w[b * NDS + n] = e;
        mysum += e;
    }
    s_sum[tid] = mysum;
    __syncthreads();
    for (int off = 128; off > 0; off >>= 1) {
        if (tid < off) s_sum[tid] += s_sum[tid + off];
        __syncthreads();
    }
    const float inv = 1.0f / s_sum[0];
    __syncthreads();
    for (int n = tid; n < NDS; n += 256) g_w[b * NDS + n] *= inv;
}

// ---------------------------------------------------------------------------
// Kernel C: fused bucket + merge-streaming scatter. One CTA per (s, quarter),
// all 4 batches together.
//   Stage 1 (hidden under other CTAs' DRAM stores): histogram the 2048-token
//   column into 394 window bins, warp-scan, group packed keys in smem.
//   Stage 2: each warp owns ~7 contiguous 128-float windows; per window it
//   walks its bin's keys (LDS broadcast), accumulates weights into registers,
//   and emits 4 coalesced STG.128. Exactly one DRAM pass per output byte;
//   no global atomics, no zero pass, no inter-kernel bucket round-trip.
// ---------------------------------------------------------------------------
__global__ __launch_bounds__(512)
void scatter_kernel(float* __restrict__ out) {
    __shared__ unsigned keys[NDS];
    __shared__ int hist[NBINS];
    __shared__ int bs[BSLEN];
    __shared__ int cur[NBINS];

    const int s    = blockIdx.x;
    const int q    = blockIdx.y;
    const int tid  = threadIdx.x;
    const int lane = tid & 31;
    const int warp = tid >> 5;

    const int head = (4 - (s & 3)) & 3;
    const int K    = (T_VOCAB - head) >> 2;        // aligned float4 chunks
    const int R    = (T_VOCAB - head) & 3;         // trailing scalars
    const int NW   = (K + 31) >> 5;                // 128-float windows
    const int NWq  = (NW + NQ - 1) / NQ;           // windows per quarter
    const int Ww   = (NWq + 15) >> 4;              // windows per warp

    // ---- stage 1a: histogram ----
    for (int i = tid; i < NBINS; i += 512) hist[i] = 0;
    __syncthreads();

    int my_tok[4], my_bin[4];
    #pragma unroll
    for (int k = 0; k < 4; k++) {
        const int n   = tid + 512 * k;
        const int tok = g_dt[s * NDS + n];
        my_tok[k] = tok;
        my_bin[k] = (tok - head + 128) >> 7;       // head tokens -> bin 0
        atomicAdd(&hist[my_bin[k]], 1);
    }
    __syncthreads();

    // ---- stage 1b: exclusive scan (warp 0, 13 bins/lane) ----
    if (warp == 0) {
        const int base = lane * 13;                // 32*13 = 416 >= 394
        int local[13];
        int sum = 0;
        #pragma unroll
        for (int k = 0; k < 13; k++) {
            const int idx = base + k;
            const int v = (idx < NBINS) ? hist[idx] : 0;
            local[k] = sum;
            sum += v;
        }
        int incl = sum;
        #pragma unroll
        for (int off = 1; off < 32; off <<= 1) {
            const int y = __shfl_up_sync(0xffffffffu, incl, off);
            if (lane >= off) incl += y;
        }
        const int excl = incl - sum;
        #pragma unroll
        for (int k = 0; k < 13; k++) {
            const int idx = base + k;
            if (idx < NBINS) { bs[idx] = excl + local[k]; cur[idx] = excl + local[k]; }
        }
        if (lane == 0) bs[NBINS] = NDS;
    }
    __syncthreads();

    // ---- stage 1c: group keys by bin into smem ----
    #pragma unroll
    for (int k = 0; k < 4; k++) {
        const int n   = tid + 512 * k;
        const int pos = atomicAdd(&cur[my_bin[k]], 1);
        keys[pos] = ((unsigned)my_tok[k] << 11) | (unsigned)n;
    }
    __syncthreads();

    // ---- stage 2: merge-stream this quarter's windows ----
    const size_t b0 = ((size_t)(0 * CTX + s)) * T_VOCAB;
    const size_t b1 = ((size_t)(1 * CTX + s)) * T_VOCAB;
    const size_t b2 = ((size_t)(2 * CTX + s)) * T_VOCAB;
    const size_t b3 = ((size_t)(3 * CTX + s)) * T_VOCAB;

    const int lim = min((q + 1) * NWq, NW);
    const int w0  = q * NWq + warp * Ww;
    const int w1  = min(w0 + Ww, lim);

    for (int w = w0; w < w1; w++) {
        const int vbase = head + 128 * w;
        const int wlen  = min(32, K - 32 * w);
        const int pst   = bs[w + 1];               // bin w+1 = window w
        const int pen   = bs[w + 2];

        float4 a0 = make_float4(0.f, 0.f, 0.f, 0.f);
        float4 a1 = a0, a2 = a0, a3 = a0;

        for (int p = pst; p < pen; p++) {
            const unsigned key = keys[p];          // LDS broadcast
            const int tok = (int)(key >> 11);
            const int rel = tok - vbase;           // in [0,128) by bucketing
            const int li  = rel >> 2;
            const int ci  = rel & 3;
            if (lane == li) {
                const int n = (int)(key & (NDS - 1));
                const float w0v = __ldg(g_w + n);
                const float w1v = __ldg(g_w + NDS + n);
                const float w2v = __ldg(g_w + 2 * NDS + n);
                const float w3v = __ldg(g_w + 3 * NDS + n);
                if (ci == 0)      { a0.x += w0v; a1.x += w1v; a2.x += w2v; a3.x += w3v; }
                else if (ci == 1) { a0.y += w0v; a1.y += w1v; a2.y += w2v; a3.y += w3v; }
                else if (ci == 2) { a0.z += w0v; a1.z += w1v; a2.z += w2v; a3.z += w3v; }
                else              { a0.w += w0v; a1.w += w1v; a2.w += w2v; a3.w += w3v; }
            }
        }

        if (lane < wlen) {
            const int off = vbase + 4 * lane;      // 16B aligned
            *reinterpret_cast<float4*>(out + b0 + off) = a0;
            *reinterpret_cast<float4*>(out + b1 + off) = a1;
            *reinterpret_cast<float4*>(out + b2 + off) = a2;
            *reinterpret_cast<float4*>(out + b3 + off) = a3;
        }

        // trailing scalars (last partial chunk): lane==wlen accumulated them
        if (w == NW - 1 && R > 0 && lane == wlen) {
            const size_t o = (size_t)(vbase + 4 * wlen);
            out[b0 + o] = a0.x; out[b1 + o] = a1.x;
            out[b2 + o] = a2.x; out[b3 + o] = a3.x;
            if (R > 1) {
                out[b0 + o + 1] = a0.y; out[b1 + o + 1] = a1.y;
                out[b2 + o + 1] = a2.y; out[b3 + o + 1] = a3.y;
            }
            if (R > 2) {
                out[b0 + o + 2] = a0.z; out[b1 + o + 2] = a1.z;
                out[b2 + o + 2] = a2.z; out[b3 + o + 2] = a3.z;
            }
        }
    }

    // head scalars (vocab ids [0, head)): bin 0, handled by quarter 0 warp 0
    if (q == 0 && warp == 0 && lane < head) {
        const int v   = lane;
        const int pen = bs[1];
        float acc0 = 0.f, acc1 = 0.f, acc2 = 0.f, acc3 = 0.f;
        for (int p = 0; p < pen; p++) {
            const unsigned key = keys[p];
            if ((int)(key >> 11) == v) {
                const int n = (int)(key & (NDS - 1));
                acc0 += __ldg(g_w + n);
                acc1 += __ldg(g_w + NDS + n);
                acc2 += __ldg(g_w + 2 * NDS + n);
                acc3 += __ldg(g_w + 3 * NDS + n);
            }
        }
        out[b0 + v] = acc0; out[b1 + v] = acc1;
        out[b2 + v] = acc2; out[b3 + v] = acc3;
    }
}

// ---------------------------------------------------------------------------
extern "C" void kernel_launch(void* const* d_in, const int* in_sizes, int n_in,
                              void* d_out, int out_size) {
    const int*   input   = (const int*)d_in[0];    // (4, 384)
    const int*   dataset = (const int*)d_in[1];    // (2048, 384)
    const float* t       = (const float*)d_in[2];  // (4,)
    float* out = (float*)d_out;                    // (4, 384, 50265) f32

    // T: transpose dataset for coalesced column reads
    dim3 tgrid(NDS / 32, CTX / 32);
    transpose_kernel<<<tgrid, dim3(32, 8)>>>(dataset);

    // A: match counts
    mc_kernel<<<NDS / 8, 256>>>(input, dataset);

    // B: softmax weights
    softmax_kernel<<<BS, 256>>>(t);

    // C: fused bucket + merge-streaming scatter
    dim3 grid(CTX, NQ);
    scatter_kernel<<<grid, 512>>>(out);
}

// round 8
// speedup vs baseline: 1.4263x; 1.1185x over previous
#include <cuda_runtime.h>
#include <math.h>

#define T_VOCAB 50265
#define CTX     384
#define BS      4
#define NDS     2048
#define NQ      4                  // vocab quarters (CTAs per position)
#define LNB     100                // local bins per quarter (head + <=99 windows)
#define BSL     (LNB + 1)

// scratch (allocation-free rule: __device__ globals)
__device__ int    g_mc[BS * NDS];
__device__ float4 g_w4[NDS];             // packed weights: {b0,b1,b2,b3} per n
__device__ int    g_dt[CTX * NDS];       // transposed dataset: g_dt[s*NDS+n]

// ---------------------------------------------------------------------------
// Kernel P: fused prep. Blocks [0,768): tiled transpose dataset (n,s)->(s,n).
// Blocks [768,1024): match counts, one warp per dataset row, int4 loads.
// ---------------------------------------------------------------------------
__global__ __launch_bounds__(256)
void prep_kernel(const int* __restrict__ input,
                 const int* __restrict__ dataset) {
    __shared__ int4 sbuf[384];           // union: transpose tile / input rows
    const int tid = threadIdx.x;

    if (blockIdx.x < 768) {
        // ---- transpose role ----
        int (*tile)[33] = reinterpret_cast<int(*)[33]>(sbuf);
        const int bt = blockIdx.x;
        const int n0 = (bt & 63) * 32;          // 2048/32 = 64
        const int s0 = (bt >> 6) * 32;          // 384/32  = 12
        const int tx = tid & 31, ty = tid >> 5; // 32 x 8
        #pragma unroll
        for (int i = 0; i < 32; i += 8)
            tile[ty + i][tx] = dataset[(n0 + ty + i) * CTX + s0 + tx];
        __syncthreads();
        #pragma unroll
        for (int i = 0; i < 32; i += 8)
            g_dt[(s0 + ty + i) * NDS + n0 + tx] = tile[tx][ty + i];
    } else {
        // ---- match-count role ----
        int4 (*s_in)[CTX / 4] = reinterpret_cast<int4(*)[CTX / 4]>(sbuf);
        for (int i = tid; i < BS * CTX / 4; i += 256)
            (&s_in[0][0])[i] = ((const int4*)input)[i];
        __syncthreads();

        const int warp = tid >> 5, lane = tid & 31;
        const int n = (blockIdx.x - 768) * 8 + warp;
        const int4* row = (const int4*)(dataset + n * CTX);

        int c0 = 0, c1 = 0, c2 = 0, c3 = 0;
        #pragma unroll
        for (int i = 0; i < 3; i++) {
            const int idx = lane + 32 * i;
            const int4 dv = row[idx];
            int4 a;
            a = s_in[0][idx];
            c0 += (dv.x == a.x) + (dv.y == a.y) + (dv.z == a.z) + (dv.w == a.w);
            a = s_in[1][idx];
            c1 += (dv.x == a.x) + (dv.y == a.y) + (dv.z == a.z) + (dv.w == a.w);
            a = s_in[2][idx];
            c2 += (dv.x == a.x) + (dv.y == a.y) + (dv.z == a.z) + (dv.w == a.w);
            a = s_in[3][idx];
            c3 += (dv.x == a.x) + (dv.y == a.y) + (dv.z == a.z) + (dv.w == a.w);
        }
        #pragma unroll
        for (int off = 16; off > 0; off >>= 1) {
            c0 += __shfl_down_sync(0xffffffffu, c0, off);
            c1 += __shfl_down_sync(0xffffffffu, c1, off);
            c2 += __shfl_down_sync(0xffffffffu, c2, off);
            c3 += __shfl_down_sync(0xffffffffu, c3, off);
        }
        if (lane == 0) {
            g_mc[0 * NDS + n] = c0;
            g_mc[1 * NDS + n] = c1;
            g_mc[2 * NDS + n] = c2;
            g_mc[3 * NDS + n] = c3;
        }
    }
}

// ---------------------------------------------------------------------------
// Kernel B: softmax over dataset axis per batch; writes packed g_w4 slots.
// ---------------------------------------------------------------------------
__global__ void softmax_kernel(const float* __restrict__ t) {
    const int b   = blockIdx.x;
    const int tid = threadIdx.x;
    const float tb = t[b];
    const float d = logf(1.0f + tb * (float)T_VOCAB / (1.0f - tb));

    __shared__ int   s_max[256];
    __shared__ float s_sum[256];
    __shared__ float w[NDS];

    int mymax = -1;
    for (int n = tid; n < NDS; n += 256) mymax = max(mymax, g_mc[b * NDS + n]);
    s_max[tid] = mymax;
    __syncthreads();
    for (int off = 128; off > 0; off >>= 1) {
        if (tid < off) s_max[tid] = max(s_max[tid], s_max[tid + off]);
        __syncthreads();
    }
    const int mcmax = s_max[0];

    float mysum = 0.0f;
    for (int n = tid; n < NDS; n += 256) {
        float e = expf((float)(g_mc[b * NDS + n] - mcmax) * d);
        w[n] = e;
        mysum += e;
    }
    s_sum[tid] = mysum;
    __syncthreads();
    for (int off = 128; off > 0; off >>= 1) {
        if (tid < off) s_sum[tid] += s_sum[tid + off];
        __syncthreads();
    }
    const float inv = 1.0f / s_sum[0];
    __syncthreads();
    float* gw = reinterpret_cast<float*>(g_w4);
    for (int n = tid; n < NDS; n += 256) gw[n * 4 + b] = w[n] * inv;
}

// ---------------------------------------------------------------------------
// Kernel C: fused quarter-filtered bucket + merge-streaming scatter.
// One CTA per (s, quarter), all 4 batches together.
//   Stage 1: scan the 2048-token column (coalesced), keep only tokens whose
//   128-float window falls in this quarter (~512), group (tok, w4) pairs in
//   smem via histogram + warp scan.
//   Stage 2: each warp owns ~7 windows; per window it walks its bin
//   (LDS broadcast tok + LDS.128 weights), accumulates into registers, and
//   emits 4 streaming STG.128 (__stcs). One DRAM pass per output byte.
// ---------------------------------------------------------------------------
__global__ __launch_bounds__(512)
void scatter_kernel(float* __restrict__ out) {
    __shared__ int    tokg[NDS];
    __shared__ float4 wg4[NDS];
    __shared__ int hist[LNB];
    __shared__ int bs[BSL];
    __shared__ int cur[LNB];

    const int s    = blockIdx.x;
    const int q    = blockIdx.y;
    const int tid  = threadIdx.x;
    const int lane = tid & 31;
    const int warp = tid >> 5;

    const int head = (4 - (s & 3)) & 3;
    const int K    = (T_VOCAB - head) >> 2;        // aligned float4 chunks
    const int R    = (T_VOCAB - head) & 3;         // trailing scalars
    const int NW   = (K + 31) >> 5;                // 128-float windows (393)
    const int NWq  = (NW + NQ - 1) / NQ;           // 99
    const int qw0  = q * NWq;
    const int qw1  = min(qw0 + NWq, NW);

    // ---- stage 1a: filtered histogram ----
    for (int i = tid; i < LNB; i += 512) hist[i] = 0;
    __syncthreads();

    int my_tok[4], my_lb[4];
    #pragma unroll
    for (int k = 0; k < 4; k++) {
        const int n   = tid + 512 * k;
        const int tok = g_dt[s * NDS + n];
        const int wi  = ((tok - head + 128) >> 7) - 1;   // -1 = head token
        int lb = -1;
        if (wi >= qw0 && wi < qw1) lb = wi - qw0 + 1;
        else if (q == 0 && wi < 0) lb = 0;
        my_tok[k] = tok;
        my_lb[k]  = lb;
        if (lb >= 0) atomicAdd(&hist[lb], 1);
    }
    __syncthreads();

    // ---- stage 1b: exclusive scan over LNB bins (warp 0, 4 bins/lane) ----
    if (warp == 0) {
        const int base = lane * 4;                 // 128 >= 100
        int local[4];
        int sum = 0;
        #pragma unroll
        for (int k = 0; k < 4; k++) {
            const int idx = base + k;
            const int v = (idx < LNB) ? hist[idx] : 0;
            local[k] = sum;
            sum += v;
        }
        int incl = sum;
        #pragma unroll
        for (int off = 1; off < 32; off <<= 1) {
            const int y = __shfl_up_sync(0xffffffffu, incl, off);
            if (lane >= off) incl += y;
        }
        const int excl = incl - sum;
        #pragma unroll
        for (int k = 0; k < 4; k++) {
            const int idx = base + k;
            if (idx < LNB) { bs[idx] = excl + local[k]; cur[idx] = excl + local[k]; }
        }
        if (lane == 31) bs[LNB] = incl;
    }
    __syncthreads();

    // ---- stage 1c: group (tok, w4) pairs by bin into smem ----
    #pragma unroll
    for (int k = 0; k < 4; k++) {
        if (my_lb[k] >= 0) {
            const int n   = tid + 512 * k;
            const int pos = atomicAdd(&cur[my_lb[k]], 1);
            tokg[pos] = my_tok[k];
            wg4[pos]  = g_w4[n];                   // LDG.128
        }
    }
    __syncthreads();

    // ---- stage 2: merge-stream this quarter's windows ----
    const size_t b0 = ((size_t)(0 * CTX + s)) * T_VOCAB;
    const size_t b1 = ((size_t)(1 * CTX + s)) * T_VOCAB;
    const size_t b2 = ((size_t)(2 * CTX + s)) * T_VOCAB;
    const size_t b3 = ((size_t)(3 * CTX + s)) * T_VOCAB;

    const int Ww = (NWq + 15) >> 4;                // windows per warp (7)
    const int w0 = qw0 + warp * Ww;
    const int w1 = min(w0 + Ww, qw1);

    for (int w = w0; w < w1; w++) {
        const int vbase = head + 128 * w;
        const int wlen  = min(32, K - 32 * w);
        const int lb    = w - qw0 + 1;
        const int pst   = bs[lb];
        const int pen   = bs[lb + 1];

        float4 a0 = make_float4(0.f, 0.f, 0.f, 0.f);
        float4 a1 = a0, a2 = a0, a3 = a0;

        for (int p = pst; p < pen; p++) {
            const int tok = tokg[p];               // LDS broadcast
            const int rel = tok - vbase;           // in [0,128)
            const int li  = rel >> 2;
            const int ci  = rel & 3;               // warp-uniform
            if (lane == li) {
                const float4 wv = wg4[p];          // LDS.128 (1 lane)
                if (ci == 0)      { a0.x += wv.x; a1.x += wv.y; a2.x += wv.z; a3.x += wv.w; }
                else if (ci == 1) { a0.y += wv.x; a1.y += wv.y; a2.y += wv.z; a3.y += wv.w; }
                else if (ci == 2) { a0.z += wv.x; a1.z += wv.y; a2.z += wv.z; a3.z += wv.w; }
                else              { a0.w += wv.x; a1.w += wv.y; a2.w += wv.z; a3.w += wv.w; }
            }
        }

        if (lane < wlen) {
            const int off = vbase + 4 * lane;      // 16B aligned
            __stcs(reinterpret_cast<float4*>(out + b0 + off), a0);
            __stcs(reinterpret_cast<float4*>(out + b1 + off), a1);
            __stcs(reinterpret_cast<float4*>(out + b2 + off), a2);
            __stcs(reinterpret_cast<float4*>(out + b3 + off), a3);
        }

        // trailing scalars (last partial chunk): lane==wlen accumulated them
        if (w == NW - 1 && R > 0 && lane == wlen) {
            const size_t o = (size_t)(vbase + 4 * wlen);
            out[b0 + o] = a0.x; out[b1 + o] = a1.x;
            out[b2 + o] = a2.x; out[b3 + o] = a3.x;
            if (R > 1) {
                out[b0 + o + 1] = a0.y; out[b1 + o + 1] = a1.y;
                out[b2 + o + 1] = a2.y; out[b3 + o + 1] = a3.y;
            }
            if (R > 2) {
                out[b0 + o + 2] = a0.z; out[b1 + o + 2] = a1.z;
                out[b2 + o + 2] = a2.z; out[b3 + o + 2] = a3.z;
            }
        }
    }

    // head scalars (vocab ids [0, head)): bin 0, quarter 0 / warp 0
    if (q == 0 && warp == 0 && lane < head) {
        const int v   = lane;
        const int pen = bs[1];
        float acc0 = 0.f, acc1 = 0.f, acc2 = 0.f, acc3 = 0.f;
        for (int p = bs[0]; p < pen; p++) {
            if (tokg[p] == v) {
                const float4 wv = wg4[p];
                acc0 += wv.x; acc1 += wv.y; acc2 += wv.z; acc3 += wv.w;
            }
        }
        out[b0 + v] = acc0; out[b1 + v] = acc1;
        out[b2 + v] = acc2; out[b3 + v] = acc3;
    }
}

// ---------------------------------------------------------------------------
extern "C" void kernel_launch(void* const* d_in, const int* in_sizes, int n_in,
                              void* d_out, int out_size) {
    const int*   input   = (const int*)d_in[0];    // (4, 384)
    const int*   dataset = (const int*)d_in[1];    // (2048, 384)
    const float* t       = (const float*)d_in[2];  // (4,)
    float* out = (float*)d_out;                    // (4, 384, 50265) f32

    // P: fused transpose + match counts
    prep_kernel<<<1024, 256>>>(input, dataset);

    // B: softmax weights (packed float4 per n)
    softmax_kernel<<<BS, 256>>>(t);

    // C: fused quarter-filtered bucket + merge-streaming scatter
    dim3 grid(CTX, NQ);
    scatter_kernel<<<grid, 512>>>(out);
}